// round 16
// baseline (speedup 1.0000x reference)
#include <cuda_runtime.h>
#include <cuda_bf16.h>
#include <math.h>

typedef unsigned long long ull;
typedef long long ll;

// ------------------------- global scratch -------------------------
__device__ float g_pref[4096*2048];
__device__ float g_pred[1024*4096];
__device__ float g_preb[4096*2048];
__device__ float g_ctxp[4096*1024];
__device__ float g_ctxq[4096*1024];
__device__ float g_hbuf[2*2*16*512];     // [parity][dir][b][512]
__device__ float g_cfin[2*16*512];       // [dir][b][512]
__device__ float g_hx  [16*1024];
__device__ float g_hy  [16*1024];
__device__ float g_scores[16*256];
__device__ float g_trgh[64*16*1024];

// bf16 hi/lo split buffers ([row][hi(K)|lo(K)])
__device__ __nv_bfloat16 g_srcx2[4096*1024];
__device__ __nv_bfloat16 g_trgx2[1024*1024];
__device__ __nv_bfloat16 g_Wf2 [2048*1024];
__device__ __nv_bfloat16 g_Wb2 [2048*1024];
__device__ __nv_bfloat16 g_Wd2 [4096*1024];
__device__ __nv_bfloat16 g_Wain2[1024*2048];
__device__ __nv_bfloat16 g_Waoq2[1024*2048];
__device__ __nv_bfloat16 g_ctx2[4096ll*2048];
__device__ __nv_bfloat16 g_A2[1024*2048];
__device__ __nv_bfloat16 g_B2[32000ll*2048];

__device__ unsigned g_arriveA[4];
__device__ volatile unsigned g_genA[4];

// ------------------------- helpers -------------------------
__device__ __forceinline__ ull pack2(float x, float y) {
    ull r; asm("mov.b64 %0, {%1,%2};" : "=l"(r) : "f"(x), "f"(y)); return r;
}
__device__ __forceinline__ void ffma2(ull& d, ull a, ull b) {
    asm("fma.rn.f32x2 %0, %1, %2, %0;" : "+l"(d) : "l"(a), "l"(b));
}
__device__ __forceinline__ float2 unpack2(ull v) {
    float2 r; asm("mov.b64 {%0,%1}, %2;" : "=f"(r.x), "=f"(r.y) : "l"(v)); return r;
}
__device__ __forceinline__ float sigf(float x) { return 1.0f / (1.0f + expf(-x)); }

__device__ __forceinline__ void gridbar(int idx, unsigned n) {
    __syncthreads();
    if (threadIdx.x == 0) {
        unsigned* arr = (unsigned*)&g_arriveA[idx];
        volatile unsigned* gen = &g_genA[idx];
        unsigned g;
        asm volatile("ld.relaxed.gpu.u32 %0, [%1];" : "=r"(g) : "l"((const unsigned*)gen));
        unsigned old;
        asm volatile("atom.add.acq_rel.gpu.u32 %0, [%1], 1;" : "=r"(old) : "l"(arr));
        if (old == n - 1u) {
            asm volatile("st.relaxed.gpu.u32 [%0], 0;" :: "l"(arr));
            unsigned ng = g + 1u;
            asm volatile("st.release.gpu.u32 [%0], %1;" :: "l"((unsigned*)gen), "r"(ng));
        } else {
            unsigned cur;
            do {
                asm volatile("ld.acquire.gpu.u32 %0, [%1];" : "=r"(cur) : "l"((const unsigned*)gen));
            } while (cur == g);
        }
    }
    __syncthreads();
}

__device__ __forceinline__ float butterfly32(float s[32], int lane) {
#pragma unroll
    for (int r = 0; r < 5; r++) {
        int m = 1 << r;
        int keep = (lane >> r) & 1;
#pragma unroll
        for (int i = 0; i < (16 >> r); i++) {
            float mine  = keep ? s[2*i+1] : s[2*i];
            float other = keep ? s[2*i]   : s[2*i+1];
            float recv  = __shfl_xor_sync(0xffffffffu, other, m);
            s[i] = mine + recv;
        }
    }
    return s[0];
}

__device__ __forceinline__ void gemv32_8x8(const ull* __restrict__ ws,
                                           const ull* __restrict__ vec, int KU,
                                           float* gates, int w, int lane) {
    int rg = w & 3, bg = w >> 2;
    ull acc[8][8];
#pragma unroll
    for (int ri = 0; ri < 8; ri++)
#pragma unroll
        for (int bi = 0; bi < 8; bi++) acc[ri][bi] = 0ull;
    const ull* wr0 = ws + (rg*8) * KU;
    const ull* vb  = vec + (bg*8) * KU;
    int iters = KU >> 5;
#pragma unroll 4
    for (int i = 0; i < iters; i++) {
        int kk = i*32 + lane;
        ull wv[8], hv[8];
#pragma unroll
        for (int ri = 0; ri < 8; ri++) wv[ri] = wr0[ri*KU + kk];
#pragma unroll
        for (int bi = 0; bi < 8; bi++) hv[bi] = vb[bi*KU + kk];
#pragma unroll
        for (int ri = 0; ri < 8; ri++)
#pragma unroll
            for (int bi = 0; bi < 8; bi++) ffma2(acc[ri][bi], wv[ri], hv[bi]);
    }
#pragma unroll
    for (int g = 0; g < 2; g++) {
        float s[32];
#pragma unroll
        for (int o = 0; o < 32; o++) {
            float2 v2 = unpack2(acc[g*4 + (o >> 3)][o & 7]);
            s[o] = v2.x + v2.y;
        }
        float r = butterfly32(s, lane);
        gates[(rg*8 + g*4 + (lane >> 3))*16 + bg*8 + (lane & 7)] = r;
    }
}

__device__ __forceinline__ void gemv8(const float* __restrict__ W, int pitchU,
                                      int rowbase, int koffU,
                                      const ull* __restrict__ vec,
                                      ull acc[4][8], int w, int lane) {
    int rg = (w >> 1) & 1, bg = w & 1;
    const ull* wr0 = (const ull*)W + (ll)(rowbase + rg*4) * pitchU + koffU;
    const ull* vb  = vec + (bg*8) * 512;
#pragma unroll 2
    for (int i = 0; i < 16; i++) {
        int kk = i*32 + lane;
        ull wv[4], hv[8];
#pragma unroll
        for (int ri = 0; ri < 4; ri++) wv[ri] = wr0[(ll)ri * pitchU + kk];
#pragma unroll
        for (int bi = 0; bi < 8; bi++) hv[bi] = vb[bi*512 + kk];
#pragma unroll
        for (int ri = 0; ri < 4; ri++)
#pragma unroll
            for (int bi = 0; bi < 8; bi++) ffma2(acc[ri][bi], wv[ri], hv[bi]);
    }
}

__device__ __forceinline__ void gemv8_store(ull acc[4][8], float* gates,
                                            int w, int lane) {
    float s[32];
#pragma unroll
    for (int o = 0; o < 32; o++) {
        float2 v2 = unpack2(acc[o >> 3][o & 7]);
        s[o] = v2.x + v2.y;
    }
    float r = butterfly32(s, lane);
    if (w < 4)
        gates[((w >> 1)*4 + (lane >> 3))*16 + (w & 1)*8 + (lane & 7)] = r;
}

// ------------------------- embedding -> bf16 split -------------------------
__global__ void embed2_k(const int* __restrict__ src, const int* __restrict__ trg,
                         const float* __restrict__ se, const float* __restrict__ te) {
    int row = blockIdx.x, t = threadIdx.x;   // 128 threads
    const float* s;
    __nv_bfloat16* d;
    if (row < 4096) { s = se + (ll)src[row]*512; d = g_srcx2 + (ll)row*1024; }
    else            { s = te + (ll)trg[row-4096]*512; d = g_trgx2 + (ll)(row-4096)*1024; }
    for (int c = t; c < 512; c += 128) {
        float x = __ldg(s + c);
        __nv_bfloat16 hi = __float2bfloat16(x);
        d[c] = hi;
        d[512 + c] = __float2bfloat16(x - __bfloat162float(hi));
    }
}

// ------------------------- weight split (row-major) -------------------------
__global__ void convW_k(const float* __restrict__ W, int pitch, int koff, int K,
                        __nv_bfloat16* __restrict__ out) {
    int r = blockIdx.x, t = threadIdx.x;  // 128 threads
    const float* s = W + (ll)r*pitch + koff;
    __nv_bfloat16* d = out + (ll)r*2*K;
    for (int c = t; c < K; c += 128) {
        float x = __ldg(s + c);
        __nv_bfloat16 hi = __float2bfloat16(x);
        d[c] = hi;
        d[K + c] = __float2bfloat16(x - __bfloat162float(hi));
    }
}

// Wain transpose+split
__global__ void convT_k(const float* __restrict__ W, __nv_bfloat16* __restrict__ out) {
    int n0 = blockIdx.x * 8;
    int ni = threadIdx.x & 7, kt = threadIdx.x >> 3;
    int n = n0 + ni;
    for (int k = kt; k < 1024; k += 32) {
        float x = __ldg(W + (ll)k*1024 + n);
        __nv_bfloat16 hi = __float2bfloat16(x);
        out[(ll)n*2048 + k] = hi;
        out[(ll)n*2048 + 1024 + k] = __float2bfloat16(x - __bfloat162float(hi));
    }
}

// ------------------------- generic HMMA NT GEMM (3-product bf16 split) -------------------------
__device__ __forceinline__ void mma16816(float* c, const unsigned* a, const unsigned* b) {
    asm volatile(
        "mma.sync.aligned.m16n8k16.row.col.f32.bf16.bf16.f32 "
        "{%0,%1,%2,%3}, {%4,%5,%6,%7}, {%8,%9}, {%0,%1,%2,%3};"
        : "+f"(c[0]), "+f"(c[1]), "+f"(c[2]), "+f"(c[3])
        : "r"(a[0]), "r"(a[1]), "r"(a[2]), "r"(a[3]), "r"(b[0]), "r"(b[1]));
}

// swap=1: m0 from blockIdx.x (fast dim) so m-tiles sharing a B block are
// co-resident -> B read once from DRAM (vocab GEMM: B2 = 131 MB >> L2).
__global__ __launch_bounds__(256, 2) void mma_nt(
    const __nv_bfloat16* __restrict__ A2, const __nv_bfloat16* __restrict__ B2,
    const float* __restrict__ bias1, const float* __restrict__ bias2,
    float* __restrict__ out, int N, int K, int swap)
{
    extern __shared__ __nv_bfloat16 vsm[];
    int tid = threadIdx.x;
    int w = tid >> 5, lane = tid & 31;
    int g = lane >> 2, t4 = lane & 3;
    int warpM = w >> 1, warpN = w & 1;
    int n0 = (swap ? blockIdx.y : blockIdx.x) * 128;
    int m0 = (swap ? blockIdx.x : blockIdx.y) * 128;
    int pitch = 2 * K;
    int nsteps = (3 * K) >> 5;

    float acc[2][8][4];
#pragma unroll
    for (int mt = 0; mt < 2; mt++)
#pragma unroll
        for (int nt = 0; nt < 8; nt++)
#pragma unroll
            for (int i = 0; i < 4; i++) acc[mt][nt][i] = 0.0f;

    int r0 = tid >> 2, q0 = tid & 3;
    int r1 = (tid + 256) >> 2, q1 = (tid + 256) & 3;

    {
        uint4 a0 = *(const uint4*)(A2 + (ll)(m0 + r0)*pitch + q0*8);
        uint4 a1 = *(const uint4*)(A2 + (ll)(m0 + r1)*pitch + q1*8);
        uint4 b0 = *(const uint4*)(B2 + (ll)(n0 + r0)*pitch + q0*8);
        uint4 b1 = *(const uint4*)(B2 + (ll)(n0 + r1)*pitch + q1*8);
        *(uint4*)(vsm + r0*40 + q0*8) = a0;
        *(uint4*)(vsm + r1*40 + q1*8) = a1;
        *(uint4*)(vsm + 5120 + r0*40 + q0*8) = b0;
        *(uint4*)(vsm + 5120 + r1*40 + q1*8) = b1;
    }
    __syncthreads();

    for (int bk = 0; bk < nsteps; bk++) {
        int cur = bk & 1, nxt = cur ^ 1;
        uint4 pa0, pa1, pb0, pb1;
        bool more = (bk + 1 < nsteps);
        if (more) {
            int k0 = (bk + 1) * 32;
            int ka = (k0 < K) ? k0 : k0 - K;
            int kb = (k0 < 2*K) ? k0 : k0 - 2*K;
            pa0 = *(const uint4*)(A2 + (ll)(m0 + r0)*pitch + ka + q0*8);
            pa1 = *(const uint4*)(A2 + (ll)(m0 + r1)*pitch + ka + q1*8);
            pb0 = *(const uint4*)(B2 + (ll)(n0 + r0)*pitch + kb + q0*8);
            pb1 = *(const uint4*)(B2 + (ll)(n0 + r1)*pitch + kb + q1*8);
        }
        const __nv_bfloat16* As = vsm + cur*10240;
        const __nv_bfloat16* Bs = As + 5120;
#pragma unroll
        for (int kh = 0; kh < 2; kh++) {
            int kc = kh*16 + t4*2;
            unsigned af[2][4];
#pragma unroll
            for (int mt = 0; mt < 2; mt++) {
                int ar = warpM*32 + mt*16 + g;
                af[mt][0] = *(const unsigned*)(As + ar*40 + kc);
                af[mt][1] = *(const unsigned*)(As + (ar+8)*40 + kc);
                af[mt][2] = *(const unsigned*)(As + ar*40 + kc + 8);
                af[mt][3] = *(const unsigned*)(As + (ar+8)*40 + kc + 8);
            }
            unsigned bf[8][2];
#pragma unroll
            for (int nt = 0; nt < 8; nt++) {
                int br = warpN*64 + nt*8 + g;
                bf[nt][0] = *(const unsigned*)(Bs + br*40 + kc);
                bf[nt][1] = *(const unsigned*)(Bs + br*40 + kc + 8);
            }
#pragma unroll
            for (int mt = 0; mt < 2; mt++)
#pragma unroll
                for (int nt = 0; nt < 8; nt++)
                    mma16816(acc[mt][nt], af[mt], bf[nt]);
        }
        if (more) {
            __nv_bfloat16* Ad = vsm + nxt*10240;
            __nv_bfloat16* Bd = Ad + 5120;
            *(uint4*)(Ad + r0*40 + q0*8) = pa0;
            *(uint4*)(Ad + r1*40 + q1*8) = pa1;
            *(uint4*)(Bd + r0*40 + q0*8) = pb0;
            *(uint4*)(Bd + r1*40 + q1*8) = pb1;
        }
        __syncthreads();
    }

#pragma unroll
    for (int mt = 0; mt < 2; mt++) {
        int row = m0 + warpM*32 + mt*16 + g;
#pragma unroll
        for (int nt = 0; nt < 8; nt++) {
            int col = n0 + warpN*64 + nt*8 + t4*2;
            float b0 = 0.f, b1 = 0.f;
            if (bias1) { b0 += __ldg(bias1 + col); b1 += __ldg(bias1 + col + 1); }
            if (bias2) { b0 += __ldg(bias2 + col); b1 += __ldg(bias2 + col + 1); }
            float2 v0 = make_float2(acc[mt][nt][0] + b0, acc[mt][nt][1] + b1);
            float2 v1 = make_float2(acc[mt][nt][2] + b0, acc[mt][nt][3] + b1);
            *(float2*)&out[(ll)row*N + col] = v0;
            *(float2*)&out[(ll)(row + 8)*N + col] = v1;
        }
    }
}

// ------------------------- persistent encoder (+ convB on spare SMs) -------------------------
__global__ __launch_bounds__(256, 1) void enc_persist(
    const float* __restrict__ Whhf, const float* __restrict__ Whhb,
    const float* __restrict__ Wvoc)
{
    extern __shared__ ull sm[];
    int tid = threadIdx.x, c = blockIdx.x;

    if (c >= 128) {
        for (ll r = c - 128; r < 32000; r += 20) {
            const float4* srcr = (const float4*)(Wvoc + r*1024);
            __nv_bfloat16* dh = g_B2 + r*2048;
            float4 v = __ldg(srcr + tid);
            int cc = tid * 4;
            float xs[4] = {v.x, v.y, v.z, v.w};
#pragma unroll
            for (int j = 0; j < 4; j++) {
                __nv_bfloat16 hi = __float2bfloat16(xs[j]);
                dh[cc + j] = hi;
                dh[1024 + cc + j] = __float2bfloat16(xs[j] - __bfloat162float(hi));
            }
        }
        return;
    }

    ull* ws = sm;
    ull* vec = sm + 8192;
    float* gates = (float*)(sm + 8192 + 4096);

    int dir = c >> 6, u0 = (c & 63) * 8;
    int w = tid >> 5, lane = tid & 31;
    int uu = tid >> 4, b = tid & 15;

    const ull* Wu = (const ull*)(dir ? Whhb : Whhf);
    for (int i = tid; i < 8192; i += 256) {
        int m = i >> 8, kk = i & 255;
        int row = (m & 3) * 512 + u0 + (m >> 2);
        ws[i] = Wu[(ll)row * 256 + kk];
    }
    const float* pre = dir ? g_preb : g_pref;
    float creg = 0.0f;

    for (int t = 0; t < 256; t++) {
        int par = t & 1;
        int sp = dir ? 255 - t : t;
        float p0 = 0.f, p1 = 0.f, p2 = 0.f, p3 = 0.f;
        if (tid < 128) {
            const float* pb = pre + ((ll)(sp*16 + b)) * 2048 + u0 + uu;
            p0 = __ldg(pb); p1 = __ldg(pb + 512);
            p2 = __ldg(pb + 1024); p3 = __ldg(pb + 1536);
        }
        if (t > 0) {
            const ull* hsrc = (const ull*)g_hbuf + (par*2 + dir) * 4096;
            for (int i = tid; i < 4096; i += 256) vec[i] = __ldcg(hsrc + i);
            __syncthreads();
            gemv32_8x8(ws, vec, 256, gates, w, lane);
        } else {
            for (int i = tid; i < 512; i += 256) gates[i] = 0.0f;
        }
        __syncthreads();
        if (tid < 128) {
            float gi = gates[(uu*4+0)*16 + b] + p0;
            float gf = gates[(uu*4+1)*16 + b] + p1;
            float gg = gates[(uu*4+2)*16 + b] + p2;
            float go = gates[(uu*4+3)*16 + b] + p3;
            float cy = sigf(gf)*creg + sigf(gi)*tanhf(gg);
            float hy = sigf(go)*tanhf(cy);
            creg = cy;
            int u = u0 + uu;
            int parn = (t + 1) & 1;
            __stcg(&g_hbuf[((parn*2 + dir)*16 + b)*512 + u], hy);
            ll crow = (ll)(b*256 + sp);
            __nv_bfloat16 hi = __float2bfloat16(hy);
            g_ctx2[crow*2048 + dir*512 + u] = hi;
            g_ctx2[crow*2048 + 1024 + dir*512 + u] =
                __float2bfloat16(hy - __bfloat162float(hi));
            if (t == 255) __stcg(&g_cfin[(dir*16 + b)*512 + u], cy);
        }
        gridbar(dir, 64);
    }
}

// ------------------------- persistent decoder -------------------------
__global__ __launch_bounds__(256, 1) void dec_persist(
    const float* __restrict__ Whid, const float* __restrict__ Waout,
    const float* __restrict__ We2d, const float* __restrict__ be2d)
{
    extern __shared__ ull sm[];
    ull* ws = sm;
    ull* vec = sm + 16384;
    float* gates = (float*)(sm + 16384 + 8192);
    float* attn  = gates + 1024;

    int tid = threadIdx.x, c = blockIdx.x;
    int u0 = c * 8;
    int w = tid >> 5, lane = tid & 31;
    int uu = tid >> 4, b16 = tid & 15;

    const ull* Wu = (const ull*)Whid;
    for (int i = tid; i < 16384; i += 256) {
        int m = i >> 9, kk = i & 511;
        int row = (m & 3) * 1024 + u0 + (m >> 2);
        ws[i] = Wu[(ll)row * 512 + kk];
    }

    {
        const ull* hb = (const ull*)g_hbuf + 1 * 4096;
        const ull* hf = (const ull*)g_hbuf + 0 * 4096;
        for (int i = tid; i < 8192; i += 256) {
            int bb = i >> 9, kk = i & 511;
            vec[i] = (kk < 256) ? __ldcg(hb + bb*256 + kk)
                                : __ldcg(hf + bb*256 + (kk - 256));
        }
        __syncthreads();
        ull acc[4][8];
#pragma unroll
        for (int ri = 0; ri < 4; ri++)
#pragma unroll
            for (int bi = 0; bi < 8; bi++) acc[ri][bi] = 0ull;
        if (w < 4) gemv8(We2d, 512, u0, 0, vec, acc, w, lane);
        gemv8_store(acc, gates, w, lane);
        __syncthreads();
        if (tid < 128) {
            float v = gates[uu*16 + b16] + be2d[u0 + uu];
            __stcg(&g_hx[b16*1024 + u0 + uu], tanhf(v));
        }
    }
    float creg = 0.0f;
    if (tid < 128) {
        int j = u0 + uu;
        creg = (j < 512) ? g_cfin[(1*16 + b16)*512 + j]
                         : g_cfin[(0*16 + b16)*512 + (j - 512)];
    }
    gridbar(2, 128);

    for (int t = 0; t < 64; t++) {
        {
            float p0 = 0.f, p1 = 0.f, p2 = 0.f, p3 = 0.f;
            if (tid < 128) {
                const float* pb = g_pred + ((ll)(t*16 + b16))*4096 + u0 + uu;
                p0 = __ldg(pb); p1 = __ldg(pb + 1024);
                p2 = __ldg(pb + 2048); p3 = __ldg(pb + 3072);
            }
            const ull* hxs = (const ull*)g_hx;
            for (int i = tid; i < 8192; i += 256) vec[i] = __ldcg(hxs + i);
            __syncthreads();
            gemv32_8x8(ws, vec, 512, gates, w, lane);
            __syncthreads();
            if (tid < 128) {
                float gi = gates[(uu*4+0)*16 + b16] + p0;
                float gf = gates[(uu*4+1)*16 + b16] + p1;
                float gg = gates[(uu*4+2)*16 + b16] + p2;
                float go = gates[(uu*4+3)*16 + b16] + p3;
                float cy = sigf(gf)*creg + sigf(gi)*tanhf(gg);
                creg = cy;
                __stcg(&g_hy[b16*1024 + u0 + uu], sigf(go)*tanhf(cy));
            }
        }
        gridbar(2, 128);
        {
            const ull* hys = (const ull*)g_hy;
            for (int i = tid; i < 8192; i += 256) vec[i] = __ldcg(hys + i);
            __syncthreads();
            int b = c >> 3, s0 = (c & 7) * 32;
            ull acc4[4] = {0ull, 0ull, 0ull, 0ull};
            const ull* cbase = (const ull*)g_ctxp + ((ll)b*256 + s0 + w*4) * 512;
            const ull* tv0 = vec + b * 512;
#pragma unroll 4
            for (int i = 0; i < 16; i++) {
                int kk = i*32 + lane;
                ull tv = tv0[kk];
#pragma unroll
                for (int si = 0; si < 4; si++)
                    ffma2(acc4[si], __ldg(cbase + (ll)si*512 + kk), tv);
            }
#pragma unroll
            for (int si = 0; si < 4; si++) {
                float2 v = unpack2(acc4[si]);
                float s = v.x + v.y;
#pragma unroll
                for (int mm = 16; mm > 0; mm >>= 1) s += __shfl_xor_sync(0xffffffffu, s, mm);
                if (lane == 0) __stcg(&g_scores[b*256 + s0 + w*4 + si], s);
            }
            ull acc[4][8];
#pragma unroll
            for (int ri = 0; ri < 4; ri++)
#pragma unroll
                for (int bi = 0; bi < 8; bi++) acc[ri][bi] = 0ull;
            if (w < 4) gemv8(Waout, 1024, u0, 512, vec, acc, w, lane);
            gemv8_store(acc, gates, w, lane);
        }
        gridbar(2, 128);
        {
#pragma unroll
            for (int hb = 0; hb < 2; hb++) {
                int bb = w*2 + hb;
                float sv[8];
                float mx = -1e30f;
#pragma unroll
                for (int i = 0; i < 8; i++) {
                    sv[i] = __ldcg(&g_scores[bb*256 + i*32 + lane]);
                    mx = fmaxf(mx, sv[i]);
                }
#pragma unroll
                for (int mm = 16; mm > 0; mm >>= 1)
                    mx = fmaxf(mx, __shfl_xor_sync(0xffffffffu, mx, mm));
                float sum = 0.f;
#pragma unroll
                for (int i = 0; i < 8; i++) { sv[i] = expf(sv[i] - mx); sum += sv[i]; }
#pragma unroll
                for (int mm = 16; mm > 0; mm >>= 1)
                    sum += __shfl_xor_sync(0xffffffffu, sum, mm);
                float inv = 1.0f / sum;
#pragma unroll
                for (int i = 0; i < 8; i++) attn[bb*256 + i*32 + lane] = sv[i] * inv;
            }
            __syncthreads();
            {
                int sh = tid >> 7, rem = tid & 127;
                int bb = rem >> 3, du = rem & 7;
                const float* cq = g_ctxq + ((ll)(bb*256 + sh*128))*1024 + u0 + du;
                const float* at = attn + bb*256 + sh*128;
                float a0 = 0.f, a1 = 0.f;
#pragma unroll 4
                for (int s = 0; s < 128; s += 2) {
                    a0 += at[s]   * __ldg(cq + (ll)s*1024);
                    a1 += at[s+1] * __ldg(cq + (ll)(s+1)*1024);
                }
                gates[128 + sh*128 + rem] = a0 + a1;
            }
            __syncthreads();
            if (tid < 128) {
                float y1 = gates[128 + b16*8 + uu] + gates[256 + b16*8 + uu];
                float v = gates[uu*16 + b16] + y1;
                float hv = tanhf(v);
                __stcg(&g_hx[b16*1024 + u0 + uu], hv);
                __stcg(&g_trgh[((ll)t*16 + b16)*1024 + u0 + uu], hv);
            }
        }
        gridbar(2, 128);
    }
}

// ------------------------- vocab A conversion -------------------------
__global__ void convA_k() {
    int r = blockIdx.x, t = threadIdx.x;
    for (int c = t; c < 1024; c += 256) {
        float x = g_trgh[r*1024 + c];
        __nv_bfloat16 hi = __float2bfloat16(x);
        g_A2[r*2048 + c] = hi;
        g_A2[r*2048 + 1024 + c] = __float2bfloat16(x - __bfloat162float(hi));
    }
}

// ------------------------- host -------------------------
extern "C" void kernel_launch(void* const* d_in, const int* in_sizes, int n_in,
                              void* d_out, int out_size) {
    const int*   src   = (const int*)d_in[0];
    const int*   trg   = (const int*)d_in[1];
    const float* semb  = (const float*)d_in[2];
    const float* temb  = (const float*)d_in[3];
    const float* Wihf  = (const float*)d_in[4];
    const float* Whhf  = (const float*)d_in[5];
    const float* bihf  = (const float*)d_in[6];
    const float* bhhf  = (const float*)d_in[7];
    const float* Wihb  = (const float*)d_in[8];
    const float* Whhb  = (const float*)d_in[9];
    const float* bihb  = (const float*)d_in[10];
    const float* bhhb  = (const float*)d_in[11];
    const float* We2d  = (const float*)d_in[12];
    const float* be2d  = (const float*)d_in[13];
    const float* Wind  = (const float*)d_in[14];
    const float* bind  = (const float*)d_in[15];
    const float* Whid  = (const float*)d_in[16];
    const float* bhid  = (const float*)d_in[17];
    const float* Wain  = (const float*)d_in[18];
    const float* Waout = (const float*)d_in[19];
    const float* Wvoc  = (const float*)d_in[20];
    const float* bvoc  = (const float*)d_in[21];
    float* out = (float*)d_out;

    float *p_pref, *p_preb, *p_pred, *p_ctxp, *p_ctxq;
    __nv_bfloat16 *p_srcx2, *p_trgx2, *p_Wf2, *p_Wb2, *p_Wd2, *p_Wain2, *p_Waoq2, *p_ctx2, *p_A2, *p_B2;
    cudaGetSymbolAddress((void**)&p_pref, g_pref);
    cudaGetSymbolAddress((void**)&p_preb, g_preb);
    cudaGetSymbolAddress((void**)&p_pred, g_pred);
    cudaGetSymbolAddress((void**)&p_ctxp, g_ctxp);
    cudaGetSymbolAddress((void**)&p_ctxq, g_ctxq);
    cudaGetSymbolAddress((void**)&p_srcx2, g_srcx2);
    cudaGetSymbolAddress((void**)&p_trgx2, g_trgx2);
    cudaGetSymbolAddress((void**)&p_Wf2,  g_Wf2);
    cudaGetSymbolAddress((void**)&p_Wb2,  g_Wb2);
    cudaGetSymbolAddress((void**)&p_Wd2,  g_Wd2);
    cudaGetSymbolAddress((void**)&p_Wain2, g_Wain2);
    cudaGetSymbolAddress((void**)&p_Waoq2, g_Waoq2);
    cudaGetSymbolAddress((void**)&p_ctx2, g_ctx2);
    cudaGetSymbolAddress((void**)&p_A2,   g_A2);
    cudaGetSymbolAddress((void**)&p_B2,   g_B2);

    const int ENC_SMEM = (8192 + 4096) * 8 + 512 * 4;                 // 100,352
    const int DEC_SMEM = (16384 + 8192) * 8 + 1024*4 + 4096*4;        // 217,088
    const int MMA_SMEM = 2 * 10240 * 2;                               // 40,960
    cudaFuncSetAttribute(enc_persist, cudaFuncAttributeMaxDynamicSharedMemorySize, ENC_SMEM);
    cudaFuncSetAttribute(dec_persist, cudaFuncAttributeMaxDynamicSharedMemorySize, DEC_SMEM);

    embed2_k<<<5120, 128>>>(src, trg, semb, temb);
    convW_k<<<2048, 128>>>(Wihf, 512, 0, 512, p_Wf2);
    convW_k<<<2048, 128>>>(Wihb, 512, 0, 512, p_Wb2);
    convW_k<<<4096, 128>>>(Wind, 512, 0, 512, p_Wd2);
    convT_k<<<128, 256>>>(Wain, p_Wain2);
    convW_k<<<1024, 128>>>(Waout, 2048, 0, 1024, p_Waoq2);

    mma_nt<<<dim3(16, 32), 256, MMA_SMEM>>>(p_srcx2, p_Wf2, bihf, bhhf, p_pref, 2048, 512, 0);
    mma_nt<<<dim3(16, 32), 256, MMA_SMEM>>>(p_srcx2, p_Wb2, bihb, bhhb, p_preb, 2048, 512, 0);
    mma_nt<<<dim3(32, 8),  256, MMA_SMEM>>>(p_trgx2, p_Wd2, bind, bhid, p_pred, 4096, 512, 0);

    enc_persist<<<148, 256, ENC_SMEM>>>(Whhf, Whhb, Wvoc);

    mma_nt<<<dim3(8, 32), 256, MMA_SMEM>>>(p_ctx2, p_Wain2, (const float*)nullptr,
                                           (const float*)nullptr, p_ctxp, 1024, 1024, 0);
    mma_nt<<<dim3(8, 32), 256, MMA_SMEM>>>(p_ctx2, p_Waoq2, (const float*)nullptr,
                                           (const float*)nullptr, p_ctxq, 1024, 1024, 0);

    dec_persist<<<128, 256, DEC_SMEM>>>(Whid, Waout, We2d, be2d);

    convA_k<<<1024, 256>>>();
    // swap=1: 8 m-tiles per n-tile co-resident -> B2 (131 MB) read once from HBM
    mma_nt<<<dim3(8, 250), 256, MMA_SMEM>>>(p_A2, p_B2, bvoc, (const float*)nullptr,
                                            out, 32000, 1024, 1);
}

// round 17
// speedup vs baseline: 1.0551x; 1.0551x over previous
#include <cuda_runtime.h>
#include <cuda_bf16.h>
#include <math.h>

typedef unsigned long long ull;
typedef long long ll;

// ------------------------- global scratch -------------------------
__device__ float g_pref[4096*2048];
__device__ float g_pred[1024*4096];
__device__ float g_preb[4096*2048];
__device__ float g_ctxp[4096*1024];
__device__ float g_ctxq[4096*1024];
__device__ float g_ctxqT[1024ll*4096];   // transposed: [u][b*256+s]
__device__ float g_hbuf[2*2*16*512];
__device__ float g_cfin[2*16*512];
__device__ float g_hx  [16*1024];
__device__ float g_hy  [16*1024];
__device__ float g_scores[16*256];
__device__ float g_trgh[64*16*1024];

// bf16 hi/lo split buffers ([row][hi(K)|lo(K)])
__device__ __nv_bfloat16 g_srcx2[4096*1024];
__device__ __nv_bfloat16 g_trgx2[1024*1024];
__device__ __nv_bfloat16 g_Wf2 [2048*1024];
__device__ __nv_bfloat16 g_Wb2 [2048*1024];
__device__ __nv_bfloat16 g_Wd2 [4096*1024];
__device__ __nv_bfloat16 g_Wain2[1024*2048];
__device__ __nv_bfloat16 g_Waoq2[1024*2048];
__device__ __nv_bfloat16 g_ctx2[4096ll*2048];
__device__ __nv_bfloat16 g_A2[1024*2048];
__device__ __nv_bfloat16 g_B2[32000ll*2048];

__device__ unsigned g_arriveA[4];
__device__ volatile unsigned g_genA[4];

// ------------------------- helpers -------------------------
__device__ __forceinline__ ull pack2(float x, float y) {
    ull r; asm("mov.b64 %0, {%1,%2};" : "=l"(r) : "f"(x), "f"(y)); return r;
}
__device__ __forceinline__ void ffma2(ull& d, ull a, ull b) {
    asm("fma.rn.f32x2 %0, %1, %2, %0;" : "+l"(d) : "l"(a), "l"(b));
}
__device__ __forceinline__ float2 unpack2(ull v) {
    float2 r; asm("mov.b64 {%0,%1}, %2;" : "=f"(r.x), "=f"(r.y) : "l"(v)); return r;
}
__device__ __forceinline__ float sigf(float x) { return 1.0f / (1.0f + expf(-x)); }

__device__ __forceinline__ void gridbar(int idx, unsigned n) {
    __syncthreads();
    if (threadIdx.x == 0) {
        unsigned* arr = (unsigned*)&g_arriveA[idx];
        volatile unsigned* gen = &g_genA[idx];
        unsigned g;
        asm volatile("ld.relaxed.gpu.u32 %0, [%1];" : "=r"(g) : "l"((const unsigned*)gen));
        unsigned old;
        asm volatile("atom.add.acq_rel.gpu.u32 %0, [%1], 1;" : "=r"(old) : "l"(arr));
        if (old == n - 1u) {
            asm volatile("st.relaxed.gpu.u32 [%0], 0;" :: "l"(arr));
            unsigned ng = g + 1u;
            asm volatile("st.release.gpu.u32 [%0], %1;" :: "l"((unsigned*)gen), "r"(ng));
        } else {
            unsigned cur;
            do {
                asm volatile("ld.acquire.gpu.u32 %0, [%1];" : "=r"(cur) : "l"((const unsigned*)gen));
            } while (cur == g);
        }
    }
    __syncthreads();
}

__device__ __forceinline__ float butterfly32(float s[32], int lane) {
#pragma unroll
    for (int r = 0; r < 5; r++) {
        int m = 1 << r;
        int keep = (lane >> r) & 1;
#pragma unroll
        for (int i = 0; i < (16 >> r); i++) {
            float mine  = keep ? s[2*i+1] : s[2*i];
            float other = keep ? s[2*i]   : s[2*i+1];
            float recv  = __shfl_xor_sync(0xffffffffu, other, m);
            s[i] = mine + recv;
        }
    }
    return s[0];
}

__device__ __forceinline__ void gemv32_8x8(const ull* __restrict__ ws,
                                           const ull* __restrict__ vec, int KU,
                                           float* gates, int w, int lane) {
    int rg = w & 3, bg = w >> 2;
    ull acc[8][8];
#pragma unroll
    for (int ri = 0; ri < 8; ri++)
#pragma unroll
        for (int bi = 0; bi < 8; bi++) acc[ri][bi] = 0ull;
    const ull* wr0 = ws + (rg*8) * KU;
    const ull* vb  = vec + (bg*8) * KU;
    int iters = KU >> 5;
#pragma unroll 4
    for (int i = 0; i < iters; i++) {
        int kk = i*32 + lane;
        ull wv[8], hv[8];
#pragma unroll
        for (int ri = 0; ri < 8; ri++) wv[ri] = wr0[ri*KU + kk];
#pragma unroll
        for (int bi = 0; bi < 8; bi++) hv[bi] = vb[bi*KU + kk];
#pragma unroll
        for (int ri = 0; ri < 8; ri++)
#pragma unroll
            for (int bi = 0; bi < 8; bi++) ffma2(acc[ri][bi], wv[ri], hv[bi]);
    }
#pragma unroll
    for (int g = 0; g < 2; g++) {
        float s[32];
#pragma unroll
        for (int o = 0; o < 32; o++) {
            float2 v2 = unpack2(acc[g*4 + (o >> 3)][o & 7]);
            s[o] = v2.x + v2.y;
        }
        float r = butterfly32(s, lane);
        gates[(rg*8 + g*4 + (lane >> 3))*16 + bg*8 + (lane & 7)] = r;
    }
}

__device__ __forceinline__ void gemv8(const float* __restrict__ W, int pitchU,
                                      int rowbase, int koffU,
                                      const ull* __restrict__ vec,
                                      ull acc[4][8], int w, int lane) {
    int rg = (w >> 1) & 1, bg = w & 1;
    const ull* wr0 = (const ull*)W + (ll)(rowbase + rg*4) * pitchU + koffU;
    const ull* vb  = vec + (bg*8) * 512;
#pragma unroll 2
    for (int i = 0; i < 16; i++) {
        int kk = i*32 + lane;
        ull wv[4], hv[8];
#pragma unroll
        for (int ri = 0; ri < 4; ri++) wv[ri] = wr0[(ll)ri * pitchU + kk];
#pragma unroll
        for (int bi = 0; bi < 8; bi++) hv[bi] = vb[bi*512 + kk];
#pragma unroll
        for (int ri = 0; ri < 4; ri++)
#pragma unroll
            for (int bi = 0; bi < 8; bi++) ffma2(acc[ri][bi], wv[ri], hv[bi]);
    }
}

__device__ __forceinline__ void gemv8_store(ull acc[4][8], float* gates,
                                            int w, int lane) {
    float s[32];
#pragma unroll
    for (int o = 0; o < 32; o++) {
        float2 v2 = unpack2(acc[o >> 3][o & 7]);
        s[o] = v2.x + v2.y;
    }
    float r = butterfly32(s, lane);
    if (w < 4)
        gates[((w >> 1)*4 + (lane >> 3))*16 + (w & 1)*8 + (lane & 7)] = r;
}

// ------------------------- embedding -> bf16 split -------------------------
__global__ void embed2_k(const int* __restrict__ src, const int* __restrict__ trg,
                         const float* __restrict__ se, const float* __restrict__ te) {
    int row = blockIdx.x, t = threadIdx.x;
    const float* s;
    __nv_bfloat16* d;
    if (row < 4096) { s = se + (ll)src[row]*512; d = g_srcx2 + (ll)row*1024; }
    else            { s = te + (ll)trg[row-4096]*512; d = g_trgx2 + (ll)(row-4096)*1024; }
    for (int c = t; c < 512; c += 128) {
        float x = __ldg(s + c);
        __nv_bfloat16 hi = __float2bfloat16(x);
        d[c] = hi;
        d[512 + c] = __float2bfloat16(x - __bfloat162float(hi));
    }
}

// ------------------------- weight split (row-major) -------------------------
__global__ void convW_k(const float* __restrict__ W, int pitch, int koff, int K,
                        __nv_bfloat16* __restrict__ out) {
    int r = blockIdx.x, t = threadIdx.x;
    const float* s = W + (ll)r*pitch + koff;
    __nv_bfloat16* d = out + (ll)r*2*K;
    for (int c = t; c < K; c += 128) {
        float x = __ldg(s + c);
        __nv_bfloat16 hi = __float2bfloat16(x);
        d[c] = hi;
        d[K + c] = __float2bfloat16(x - __bfloat162float(hi));
    }
}

// Wain transpose+split
__global__ void convT_k(const float* __restrict__ W, __nv_bfloat16* __restrict__ out) {
    int n0 = blockIdx.x * 8;
    int ni = threadIdx.x & 7, kt = threadIdx.x >> 3;
    int n = n0 + ni;
    for (int k = kt; k < 1024; k += 32) {
        float x = __ldg(W + (ll)k*1024 + n);
        __nv_bfloat16 hi = __float2bfloat16(x);
        out[(ll)n*2048 + k] = hi;
        out[(ll)n*2048 + 1024 + k] = __float2bfloat16(x - __bfloat162float(hi));
    }
}

// ctxq[4096][1024] -> ctxqT[1024][4096], tiled transpose
__global__ void transq_k() {
    __shared__ float tile[32][33];
    int bx = blockIdx.x, by = blockIdx.y;   // bx: 32 u-tiles, by: 128 row-tiles
    int x = threadIdx.x, y = threadIdx.y;   // 32 x 8
#pragma unroll
    for (int j = 0; j < 32; j += 8)
        tile[y + j][x] = g_ctxq[(ll)(by*32 + y + j)*1024 + bx*32 + x];
    __syncthreads();
#pragma unroll
    for (int j = 0; j < 32; j += 8)
        g_ctxqT[(ll)(bx*32 + y + j)*4096 + by*32 + x] = tile[x][y + j];
}

// ------------------------- generic HMMA NT GEMM (3-product bf16 split) -------------------------
__device__ __forceinline__ void mma16816(float* c, const unsigned* a, const unsigned* b) {
    asm volatile(
        "mma.sync.aligned.m16n8k16.row.col.f32.bf16.bf16.f32 "
        "{%0,%1,%2,%3}, {%4,%5,%6,%7}, {%8,%9}, {%0,%1,%2,%3};"
        : "+f"(c[0]), "+f"(c[1]), "+f"(c[2]), "+f"(c[3])
        : "r"(a[0]), "r"(a[1]), "r"(a[2]), "r"(a[3]), "r"(b[0]), "r"(b[1]));
}

__global__ __launch_bounds__(256, 2) void mma_nt(
    const __nv_bfloat16* __restrict__ A2, const __nv_bfloat16* __restrict__ B2,
    const float* __restrict__ bias1, const float* __restrict__ bias2,
    float* __restrict__ out, int N, int K)
{
    extern __shared__ __nv_bfloat16 vsm[];
    int tid = threadIdx.x;
    int w = tid >> 5, lane = tid & 31;
    int g = lane >> 2, t4 = lane & 3;
    int warpM = w >> 1, warpN = w & 1;
    int n0 = blockIdx.x * 128, m0 = blockIdx.y * 128;
    int pitch = 2 * K;
    int nsteps = (3 * K) >> 5;

    float acc[2][8][4];
#pragma unroll
    for (int mt = 0; mt < 2; mt++)
#pragma unroll
        for (int nt = 0; nt < 8; nt++)
#pragma unroll
            for (int i = 0; i < 4; i++) acc[mt][nt][i] = 0.0f;

    int r0 = tid >> 2, q0 = tid & 3;
    int r1 = (tid + 256) >> 2, q1 = (tid + 256) & 3;

    {
        uint4 a0 = *(const uint4*)(A2 + (ll)(m0 + r0)*pitch + q0*8);
        uint4 a1 = *(const uint4*)(A2 + (ll)(m0 + r1)*pitch + q1*8);
        uint4 b0 = *(const uint4*)(B2 + (ll)(n0 + r0)*pitch + q0*8);
        uint4 b1 = *(const uint4*)(B2 + (ll)(n0 + r1)*pitch + q1*8);
        *(uint4*)(vsm + r0*40 + q0*8) = a0;
        *(uint4*)(vsm + r1*40 + q1*8) = a1;
        *(uint4*)(vsm + 5120 + r0*40 + q0*8) = b0;
        *(uint4*)(vsm + 5120 + r1*40 + q1*8) = b1;
    }
    __syncthreads();

    for (int bk = 0; bk < nsteps; bk++) {
        int cur = bk & 1, nxt = cur ^ 1;
        uint4 pa0, pa1, pb0, pb1;
        bool more = (bk + 1 < nsteps);
        if (more) {
            int k0 = (bk + 1) * 32;
            int ka = (k0 < K) ? k0 : k0 - K;
            int kb = (k0 < 2*K) ? k0 : k0 - 2*K;
            pa0 = *(const uint4*)(A2 + (ll)(m0 + r0)*pitch + ka + q0*8);
            pa1 = *(const uint4*)(A2 + (ll)(m0 + r1)*pitch + ka + q1*8);
            pb0 = *(const uint4*)(B2 + (ll)(n0 + r0)*pitch + kb + q0*8);
            pb1 = *(const uint4*)(B2 + (ll)(n0 + r1)*pitch + kb + q1*8);
        }
        const __nv_bfloat16* As = vsm + cur*10240;
        const __nv_bfloat16* Bs = As + 5120;
#pragma unroll
        for (int kh = 0; kh < 2; kh++) {
            int kc = kh*16 + t4*2;
            unsigned af[2][4];
#pragma unroll
            for (int mt = 0; mt < 2; mt++) {
                int ar = warpM*32 + mt*16 + g;
                af[mt][0] = *(const unsigned*)(As + ar*40 + kc);
                af[mt][1] = *(const unsigned*)(As + (ar+8)*40 + kc);
                af[mt][2] = *(const unsigned*)(As + ar*40 + kc + 8);
                af[mt][3] = *(const unsigned*)(As + (ar+8)*40 + kc + 8);
            }
            unsigned bf[8][2];
#pragma unroll
            for (int nt = 0; nt < 8; nt++) {
                int br = warpN*64 + nt*8 + g;
                bf[nt][0] = *(const unsigned*)(Bs + br*40 + kc);
                bf[nt][1] = *(const unsigned*)(Bs + br*40 + kc + 8);
            }
#pragma unroll
            for (int mt = 0; mt < 2; mt++)
#pragma unroll
                for (int nt = 0; nt < 8; nt++)
                    mma16816(acc[mt][nt], af[mt], bf[nt]);
        }
        if (more) {
            __nv_bfloat16* Ad = vsm + nxt*10240;
            __nv_bfloat16* Bd = Ad + 5120;
            *(uint4*)(Ad + r0*40 + q0*8) = pa0;
            *(uint4*)(Ad + r1*40 + q1*8) = pa1;
            *(uint4*)(Bd + r0*40 + q0*8) = pb0;
            *(uint4*)(Bd + r1*40 + q1*8) = pb1;
        }
        __syncthreads();
    }

#pragma unroll
    for (int mt = 0; mt < 2; mt++) {
        int row = m0 + warpM*32 + mt*16 + g;
#pragma unroll
        for (int nt = 0; nt < 8; nt++) {
            int col = n0 + warpN*64 + nt*8 + t4*2;
            float b0 = 0.f, b1 = 0.f;
            if (bias1) { b0 += __ldg(bias1 + col); b1 += __ldg(bias1 + col + 1); }
            if (bias2) { b0 += __ldg(bias2 + col); b1 += __ldg(bias2 + col + 1); }
            float2 v0 = make_float2(acc[mt][nt][0] + b0, acc[mt][nt][1] + b1);
            float2 v1 = make_float2(acc[mt][nt][2] + b0, acc[mt][nt][3] + b1);
            *(float2*)&out[(ll)row*N + col] = v0;
            *(float2*)&out[(ll)(row + 8)*N + col] = v1;
        }
    }
}

// ------------------------- persistent encoder (+ convB on spare SMs) -------------------------
__global__ __launch_bounds__(256, 1) void enc_persist(
    const float* __restrict__ Whhf, const float* __restrict__ Whhb,
    const float* __restrict__ Wvoc)
{
    extern __shared__ ull sm[];
    int tid = threadIdx.x, c = blockIdx.x;

    if (c >= 128) {
        for (ll r = c - 128; r < 32000; r += 20) {
            const float4* srcr = (const float4*)(Wvoc + r*1024);
            __nv_bfloat16* dh = g_B2 + r*2048;
            float4 v = __ldg(srcr + tid);
            int cc = tid * 4;
            float xs[4] = {v.x, v.y, v.z, v.w};
#pragma unroll
            for (int j = 0; j < 4; j++) {
                __nv_bfloat16 hi = __float2bfloat16(xs[j]);
                dh[cc + j] = hi;
                dh[1024 + cc + j] = __float2bfloat16(xs[j] - __bfloat162float(hi));
            }
        }
        return;
    }

    ull* ws = sm;
    ull* vec = sm + 8192;
    float* gates = (float*)(sm + 8192 + 4096);

    int dir = c >> 6, u0 = (c & 63) * 8;
    int w = tid >> 5, lane = tid & 31;
    int uu = tid >> 4, b = tid & 15;

    const ull* Wu = (const ull*)(dir ? Whhb : Whhf);
    for (int i = tid; i < 8192; i += 256) {
        int m = i >> 8, kk = i & 255;
        int row = (m & 3) * 512 + u0 + (m >> 2);
        ws[i] = Wu[(ll)row * 256 + kk];
    }
    const float* pre = dir ? g_preb : g_pref;
    float creg = 0.0f;

    for (int t = 0; t < 256; t++) {
        int par = t & 1;
        int sp = dir ? 255 - t : t;
        float p0 = 0.f, p1 = 0.f, p2 = 0.f, p3 = 0.f;
        if (tid < 128) {
            const float* pb = pre + ((ll)(sp*16 + b)) * 2048 + u0 + uu;
            p0 = __ldg(pb); p1 = __ldg(pb + 512);
            p2 = __ldg(pb + 1024); p3 = __ldg(pb + 1536);
        }
        if (t > 0) {
            const ull* hsrc = (const ull*)g_hbuf + (par*2 + dir) * 4096;
            for (int i = tid; i < 4096; i += 256) vec[i] = __ldcg(hsrc + i);
            __syncthreads();
            gemv32_8x8(ws, vec, 256, gates, w, lane);
        } else {
            for (int i = tid; i < 512; i += 256) gates[i] = 0.0f;
        }
        __syncthreads();
        if (tid < 128) {
            float gi = gates[(uu*4+0)*16 + b] + p0;
            float gf = gates[(uu*4+1)*16 + b] + p1;
            float gg = gates[(uu*4+2)*16 + b] + p2;
            float go = gates[(uu*4+3)*16 + b] + p3;
            float cy = sigf(gf)*creg + sigf(gi)*tanhf(gg);
            float hy = sigf(go)*tanhf(cy);
            creg = cy;
            int u = u0 + uu;
            int parn = (t + 1) & 1;
            __stcg(&g_hbuf[((parn*2 + dir)*16 + b)*512 + u], hy);
            ll crow = (ll)(b*256 + sp);
            __nv_bfloat16 hi = __float2bfloat16(hy);
            g_ctx2[crow*2048 + dir*512 + u] = hi;
            g_ctx2[crow*2048 + 1024 + dir*512 + u] =
                __float2bfloat16(hy - __bfloat162float(hi));
            if (t == 255) __stcg(&g_cfin[(dir*16 + b)*512 + u], cy);
        }
        gridbar(dir, 64);
    }
}

// ------------------------- persistent decoder -------------------------
__global__ __launch_bounds__(256, 1) void dec_persist(
    const float* __restrict__ Whid, const float* __restrict__ Waout,
    const float* __restrict__ We2d, const float* __restrict__ be2d)
{
    extern __shared__ ull sm[];
    ull* ws = sm;
    ull* vec = sm + 16384;
    float* gates = (float*)(sm + 16384 + 8192);
    float* attn  = gates + 1024;

    int tid = threadIdx.x, c = blockIdx.x;
    int u0 = c * 8;
    int w = tid >> 5, lane = tid & 31;
    int uu = tid >> 4, b16 = tid & 15;

    const ull* Wu = (const ull*)Whid;
    for (int i = tid; i < 16384; i += 256) {
        int m = i >> 9, kk = i & 511;
        int row = (m & 3) * 1024 + u0 + (m >> 2);
        ws[i] = Wu[(ll)row * 512 + kk];
    }

    {
        const ull* hb = (const ull*)g_hbuf + 1 * 4096;
        const ull* hf = (const ull*)g_hbuf + 0 * 4096;
        for (int i = tid; i < 8192; i += 256) {
            int bb = i >> 9, kk = i & 511;
            vec[i] = (kk < 256) ? __ldcg(hb + bb*256 + kk)
                                : __ldcg(hf + bb*256 + (kk - 256));
        }
        __syncthreads();
        ull acc[4][8];
#pragma unroll
        for (int ri = 0; ri < 4; ri++)
#pragma unroll
            for (int bi = 0; bi < 8; bi++) acc[ri][bi] = 0ull;
        if (w < 4) gemv8(We2d, 512, u0, 0, vec, acc, w, lane);
        gemv8_store(acc, gates, w, lane);
        __syncthreads();
        if (tid < 128) {
            float v = gates[uu*16 + b16] + be2d[u0 + uu];
            __stcg(&g_hx[b16*1024 + u0 + uu], tanhf(v));
        }
    }
    float creg = 0.0f;
    if (tid < 128) {
        int j = u0 + uu;
        creg = (j < 512) ? g_cfin[(1*16 + b16)*512 + j]
                         : g_cfin[(0*16 + b16)*512 + (j - 512)];
    }
    gridbar(2, 128);

    for (int t = 0; t < 64; t++) {
        // ---- P0: gates + LSTM pointwise -> hy ----
        {
            float p0 = 0.f, p1 = 0.f, p2 = 0.f, p3 = 0.f;
            if (tid < 128) {
                const float* pb = g_pred + ((ll)(t*16 + b16))*4096 + u0 + uu;
                p0 = __ldg(pb); p1 = __ldg(pb + 1024);
                p2 = __ldg(pb + 2048); p3 = __ldg(pb + 3072);
            }
            const ull* hxs = (const ull*)g_hx;
            for (int i = tid; i < 8192; i += 256) vec[i] = __ldcg(hxs + i);
            __syncthreads();
            gemv32_8x8(ws, vec, 512, gates, w, lane);
            __syncthreads();
            if (tid < 128) {
                float gi = gates[(uu*4+0)*16 + b16] + p0;
                float gf = gates[(uu*4+1)*16 + b16] + p1;
                float gg = gates[(uu*4+2)*16 + b16] + p2;
                float go = gates[(uu*4+3)*16 + b16] + p3;
                float cy = sigf(gf)*creg + sigf(gi)*tanhf(gg);
                creg = cy;
                __stcg(&g_hy[b16*1024 + u0 + uu], sigf(go)*tanhf(cy));
            }
        }
        gridbar(2, 128);
        // ---- P1: stage hy once; scores slice + htilde gemv ----
        {
            const ull* hys = (const ull*)g_hy;
            for (int i = tid; i < 8192; i += 256) vec[i] = __ldcg(hys + i);
            __syncthreads();
            int b = c >> 3, s0 = (c & 7) * 32;
            ull acc4[4] = {0ull, 0ull, 0ull, 0ull};
            const ull* cbase = (const ull*)g_ctxp + ((ll)b*256 + s0 + w*4) * 512;
            const ull* tv0 = vec + b * 512;
#pragma unroll 4
            for (int i = 0; i < 16; i++) {
                int kk = i*32 + lane;
                ull tv = tv0[kk];
#pragma unroll
                for (int si = 0; si < 4; si++)
                    ffma2(acc4[si], __ldg(cbase + (ll)si*512 + kk), tv);
            }
#pragma unroll
            for (int si = 0; si < 4; si++) {
                float2 v = unpack2(acc4[si]);
                float s = v.x + v.y;
#pragma unroll
                for (int mm = 16; mm > 0; mm >>= 1) s += __shfl_xor_sync(0xffffffffu, s, mm);
                if (lane == 0) __stcg(&g_scores[b*256 + s0 + w*4 + si], s);
            }
            ull acc[4][8];
#pragma unroll
            for (int ri = 0; ri < 4; ri++)
#pragma unroll
                for (int bi = 0; bi < 8; bi++) acc[ri][bi] = 0ull;
            if (w < 4) gemv8(Waout, 1024, u0, 512, vec, acc, w, lane);
            gemv8_store(acc, gates, w, lane);
        }
        gridbar(2, 128);
        // ---- P2: softmax + coalesced y1 (ctxqT) + combine ----
        {
#pragma unroll
            for (int hb = 0; hb < 2; hb++) {
                int bb = w*2 + hb;
                float sv[8];
                float mx = -1e30f;
#pragma unroll
                for (int i = 0; i < 8; i++) {
                    sv[i] = __ldcg(&g_scores[bb*256 + i*32 + lane]);
                    mx = fmaxf(mx, sv[i]);
                }
#pragma unroll
                for (int mm = 16; mm > 0; mm >>= 1)
                    mx = fmaxf(mx, __shfl_xor_sync(0xffffffffu, mx, mm));
                float sum = 0.f;
#pragma unroll
                for (int i = 0; i < 8; i++) { sv[i] = expf(sv[i] - mx); sum += sv[i]; }
#pragma unroll
                for (int mm = 16; mm > 0; mm >>= 1)
                    sum += __shfl_xor_sync(0xffffffffu, sum, mm);
                float inv = 1.0f / sum;
#pragma unroll
                for (int i = 0; i < 8; i++) attn[bb*256 + i*32 + lane] = sv[i] * inv;
            }
            __syncthreads();
            // y1 via butterfly gemv on ctxqT: warp w -> outputs og=w&3 (32),
            // s-half sh=w>>2; lanes sweep consecutive s (coalesced).
            {
                int og = w & 3, sh = w >> 2;
                float acc[32];
#pragma unroll
                for (int oo = 0; oo < 32; oo++) acc[oo] = 0.0f;
#pragma unroll
                for (int i = 0; i < 4; i++) {
                    int svec = sh*128 + i*32 + lane;
#pragma unroll
                    for (int oo = 0; oo < 32; oo++) {
                        int o = og*32 + oo;
                        int bb = o >> 3, du = o & 7;
                        acc[oo] += __ldg(&g_ctxqT[(ll)(u0 + du)*4096 + bb*256 + svec])
                                 * attn[bb*256 + svec];
                    }
                }
                float r = butterfly32(acc, lane);
                gates[128 + w*32 + lane] = r;   // output o = og*32+lane, half sh
            }
            __syncthreads();
            if (tid < 128) {
                int o = b16*8 + uu;
                float y1 = gates[128 + o] + gates[256 + o];
                float v = gates[uu*16 + b16] + y1;
                float hv = tanhf(v);
                __stcg(&g_hx[b16*1024 + u0 + uu], hv);
                __stcg(&g_trgh[((ll)t*16 + b16)*1024 + u0 + uu], hv);
            }
        }
        gridbar(2, 128);
    }
}

// ------------------------- vocab A conversion -------------------------
__global__ void convA_k() {
    int r = blockIdx.x, t = threadIdx.x;
    for (int c = t; c < 1024; c += 256) {
        float x = g_trgh[r*1024 + c];
        __nv_bfloat16 hi = __float2bfloat16(x);
        g_A2[r*2048 + c] = hi;
        g_A2[r*2048 + 1024 + c] = __float2bfloat16(x - __bfloat162float(hi));
    }
}

// ------------------------- host -------------------------
extern "C" void kernel_launch(void* const* d_in, const int* in_sizes, int n_in,
                              void* d_out, int out_size) {
    const int*   src   = (const int*)d_in[0];
    const int*   trg   = (const int*)d_in[1];
    const float* semb  = (const float*)d_in[2];
    const float* temb  = (const float*)d_in[3];
    const float* Wihf  = (const float*)d_in[4];
    const float* Whhf  = (const float*)d_in[5];
    const float* bihf  = (const float*)d_in[6];
    const float* bhhf  = (const float*)d_in[7];
    const float* Wihb  = (const float*)d_in[8];
    const float* Whhb  = (const float*)d_in[9];
    const float* bihb  = (const float*)d_in[10];
    const float* bhhb  = (const float*)d_in[11];
    const float* We2d  = (const float*)d_in[12];
    const float* be2d  = (const float*)d_in[13];
    const float* Wind  = (const float*)d_in[14];
    const float* bind  = (const float*)d_in[15];
    const float* Whid  = (const float*)d_in[16];
    const float* bhid  = (const float*)d_in[17];
    const float* Wain  = (const float*)d_in[18];
    const float* Waout = (const float*)d_in[19];
    const float* Wvoc  = (const float*)d_in[20];
    const float* bvoc  = (const float*)d_in[21];
    float* out = (float*)d_out;

    float *p_pref, *p_preb, *p_pred, *p_ctxp, *p_ctxq;
    __nv_bfloat16 *p_srcx2, *p_trgx2, *p_Wf2, *p_Wb2, *p_Wd2, *p_Wain2, *p_Waoq2, *p_ctx2, *p_A2, *p_B2;
    cudaGetSymbolAddress((void**)&p_pref, g_pref);
    cudaGetSymbolAddress((void**)&p_preb, g_preb);
    cudaGetSymbolAddress((void**)&p_pred, g_pred);
    cudaGetSymbolAddress((void**)&p_ctxp, g_ctxp);
    cudaGetSymbolAddress((void**)&p_ctxq, g_ctxq);
    cudaGetSymbolAddress((void**)&p_srcx2, g_srcx2);
    cudaGetSymbolAddress((void**)&p_trgx2, g_trgx2);
    cudaGetSymbolAddress((void**)&p_Wf2,  g_Wf2);
    cudaGetSymbolAddress((void**)&p_Wb2,  g_Wb2);
    cudaGetSymbolAddress((void**)&p_Wd2,  g_Wd2);
    cudaGetSymbolAddress((void**)&p_Wain2, g_Wain2);
    cudaGetSymbolAddress((void**)&p_Waoq2, g_Waoq2);
    cudaGetSymbolAddress((void**)&p_ctx2, g_ctx2);
    cudaGetSymbolAddress((void**)&p_A2,   g_A2);
    cudaGetSymbolAddress((void**)&p_B2,   g_B2);

    const int ENC_SMEM = (8192 + 4096) * 8 + 512 * 4;
    const int DEC_SMEM = (16384 + 8192) * 8 + 1024*4 + 4096*4;
    const int MMA_SMEM = 2 * 10240 * 2;
    cudaFuncSetAttribute(enc_persist, cudaFuncAttributeMaxDynamicSharedMemorySize, ENC_SMEM);
    cudaFuncSetAttribute(dec_persist, cudaFuncAttributeMaxDynamicSharedMemorySize, DEC_SMEM);

    embed2_k<<<5120, 128>>>(src, trg, semb, temb);
    convW_k<<<2048, 128>>>(Wihf, 512, 0, 512, p_Wf2);
    convW_k<<<2048, 128>>>(Wihb, 512, 0, 512, p_Wb2);
    convW_k<<<4096, 128>>>(Wind, 512, 0, 512, p_Wd2);
    convT_k<<<128, 256>>>(Wain, p_Wain2);
    convW_k<<<1024, 128>>>(Waout, 2048, 0, 1024, p_Waoq2);

    mma_nt<<<dim3(16, 32), 256, MMA_SMEM>>>(p_srcx2, p_Wf2, bihf, bhhf, p_pref, 2048, 512);
    mma_nt<<<dim3(16, 32), 256, MMA_SMEM>>>(p_srcx2, p_Wb2, bihb, bhhb, p_preb, 2048, 512);
    mma_nt<<<dim3(32, 8),  256, MMA_SMEM>>>(p_trgx2, p_Wd2, bind, bhid, p_pred, 4096, 512);

    enc_persist<<<148, 256, ENC_SMEM>>>(Whhf, Whhb, Wvoc);

    mma_nt<<<dim3(8, 32), 256, MMA_SMEM>>>(p_ctx2, p_Wain2, (const float*)nullptr,
                                           (const float*)nullptr, p_ctxp, 1024, 1024);
    mma_nt<<<dim3(8, 32), 256, MMA_SMEM>>>(p_ctx2, p_Waoq2, (const float*)nullptr,
                                           (const float*)nullptr, p_ctxq, 1024, 1024);
    transq_k<<<dim3(32, 128), dim3(32, 8)>>>();

    dec_persist<<<128, 256, DEC_SMEM>>>(Whid, Waout, We2d, be2d);

    convA_k<<<1024, 256>>>();
    mma_nt<<<dim3(250, 8), 256, MMA_SMEM>>>(p_A2, p_B2, bvoc, (const float*)nullptr,
                                            out, 32000, 1024);
}